// round 1
// baseline (speedup 1.0000x reference)
#include <cuda_runtime.h>

// Problem constants
#define N_    2
#define T_    7
#define C_    96
#define HW_   9216
#define W_    96
#define PTOT  18432      // N_*HW_
#define NHEAD 4
#define HD_   24
#define K3C   288        // 3*C_

// Scratch (static device arrays; no runtime allocation)
__device__ float g_cat[K3C * PTOT];       // [k][g]  k = set*96 + channel
__device__ float g_soft[NHEAD * PTOT];    // [head][g]
__device__ float g_u[C_ * PTOT];          // [c][g]

// ---------------------------------------------------------------------------
// K1: per-pixel correlation + argmax + winning-frame gather
// ---------------------------------------------------------------------------
__global__ void __launch_bounds__(128)
k1_corr(const float* __restrict__ curr,
        const float* __restrict__ idxf,
        const float* __restrict__ s1,
        const float* __restrict__ s2,
        const float* __restrict__ s3,
        const float* __restrict__ loc)
{
    int g = blockIdx.x * 128 + threadIdx.x;
    if (g >= PTOT) return;
    int n = g / HW_;
    int p = g % HW_;

    int  lin[T_];
    bool val[T_];
    int  base[T_];
#pragma unroll
    for (int t = 0; t < T_; t++) {
        float lx = loc[(n * 2 * T_ + 2 * t) * HW_ + p];
        float ly = loc[(n * 2 * T_ + 2 * t + 1) * HW_ + p];
        // replicate reference fp32 op order exactly (no fmad contraction)
        float gx = __fadd_rn(__fdiv_rn(__fmul_rn(2.0f, lx), 95.0f), -1.0f);
        float gy = __fadd_rn(__fdiv_rn(__fmul_rn(2.0f, ly), 95.0f), -1.0f);
        float ixf = rintf(__fmul_rn(__fmul_rn(__fadd_rn(gx, 1.0f), 0.5f), 95.0f));
        float iyf = rintf(__fmul_rn(__fmul_rn(__fadd_rn(gy, 1.0f), 0.5f), 95.0f));
        bool v = (ixf >= 0.0f) && (ixf <= 95.0f) && (iyf >= 0.0f) && (iyf <= 95.0f);
        int ix = (int)fminf(fmaxf(ixf, 0.0f), 95.0f);
        int iy = (int)fminf(fmaxf(iyf, 0.0f), 95.0f);
        lin[t]  = iy * W_ + ix;
        val[t]  = v;
        base[t] = ((n * T_ + t) * C_) * HW_ + lin[t];
    }

    float qsq = 0.0f;
    float ksq[T_];
    float s[NHEAD][T_];
#pragma unroll
    for (int t = 0; t < T_; t++) ksq[t] = 0.0f;
#pragma unroll
    for (int h = 0; h < NHEAD; h++)
#pragma unroll
        for (int t = 0; t < T_; t++) s[h][t] = 0.0f;

    for (int h = 0; h < NHEAD; h++) {
#pragma unroll 4
        for (int cc = 0; cc < HD_; cc++) {
            int c = h * HD_ + cc;
            float q = curr[(n * C_ + c) * HW_ + p];
            qsq = fmaf(q, q, qsq);
#pragma unroll
            for (int t = 0; t < T_; t++) {
                float k = val[t] ? idxf[base[t] + c * HW_] : 0.0f;
                ksq[t]  = fmaf(k, k, ksq[t]);
                s[h][t] = fmaf(q, k, s[h][t]);
            }
        }
    }

    float rq = 1.0f / fmaxf(sqrtf(qsq), 1e-12f);
    float rk[T_];
#pragma unroll
    for (int t = 0; t < T_; t++)
        rk[t] = rq / fmaxf(sqrtf(ksq[t]), 1e-12f);

#pragma unroll
    for (int h = 0; h < NHEAD; h++) {
        float best = s[h][0] * rk[0];
        int bi = 0;
#pragma unroll
        for (int t = 1; t < T_; t++) {
            float sc = s[h][t] * rk[t];
            if (sc > best) { best = sc; bi = t; }   // strict > => first-max (torch/jnp argmax)
        }
        g_soft[h * PTOT + g] = best;

        bool v = val[bi];
        int  bofs = ((n * T_ + bi) * C_) * HW_ + lin[bi];
        const float* b1 = s1 + bofs;
        const float* b2 = s2 + bofs;
        const float* b3 = s3 + bofs;
#pragma unroll 4
        for (int cc = 0; cc < HD_; cc++) {
            int c = h * HD_ + cc;
            float v1 = v ? b1[c * HW_] : 0.0f;
            float v2 = v ? b2[c * HW_] : 0.0f;
            float v3 = v ? b3[c * HW_] : 0.0f;
            g_cat[(0 * C_ + c) * PTOT + g] = v1;
            g_cat[(1 * C_ + c) * PTOT + g] = v2;
            g_cat[(2 * C_ + c) * PTOT + g] = v3;
        }
    }
}

// ---------------------------------------------------------------------------
// K2: U[96][P] = fusion_w[96][288] @ cat[288][P] + fb, scaled by per-head soft
// ---------------------------------------------------------------------------
#define PB 128
#define KB 32

__global__ void __launch_bounds__(256)
k2_fusion(const float* __restrict__ Fw, const float* __restrict__ fb)
{
    __shared__ float As[KB * 100];   // [kk][m], pitch 100 to dodge bank conflicts
    __shared__ float Bs[KB * 132];   // [kk][col], pitch 132 (16B aligned rows)

    int g0 = blockIdx.x * PB;
    int tx = threadIdx.x;
    int m0   = (tx >> 4) * 6;    // 16 groups * 6 rows = 96
    int col0 = (tx & 15) * 8;    // 16 groups * 8 cols = 128

    float acc[6][8];
#pragma unroll
    for (int j = 0; j < 6; j++)
#pragma unroll
        for (int jj = 0; jj < 8; jj++) acc[j][jj] = 0.0f;

    for (int kb = 0; kb < K3C; kb += KB) {
        for (int i = tx; i < C_ * KB; i += 256) {
            int m = i >> 5, kk = i & 31;
            As[kk * 100 + m] = Fw[m * K3C + kb + kk];
        }
        for (int i = tx; i < KB * PB; i += 256) {
            int kk = i >> 7, col = i & 127;
            Bs[kk * 132 + col] = g_cat[(kb + kk) * PTOT + g0 + col];
        }
        __syncthreads();
#pragma unroll
        for (int kk = 0; kk < KB; kk++) {
            float a[6];
#pragma unroll
            for (int j = 0; j < 6; j++) a[j] = As[kk * 100 + m0 + j];
            float4 b0 = *(const float4*)&Bs[kk * 132 + col0];
            float4 b1 = *(const float4*)&Bs[kk * 132 + col0 + 4];
            float bb[8] = {b0.x, b0.y, b0.z, b0.w, b1.x, b1.y, b1.z, b1.w};
#pragma unroll
            for (int j = 0; j < 6; j++)
#pragma unroll
                for (int jj = 0; jj < 8; jj++)
                    acc[j][jj] = fmaf(a[j], bb[jj], acc[j][jj]);
        }
        __syncthreads();
    }

    int head = m0 / HD_;              // 6 | 24, so one head per thread-row-group
    float sf[8];
#pragma unroll
    for (int jj = 0; jj < 8; jj++) sf[jj] = g_soft[head * PTOT + g0 + col0 + jj];

#pragma unroll
    for (int j = 0; j < 6; j++) {
        float fbm = fb[m0 + j];
        float4 r0, r1;
        r0.x = (acc[j][0] + fbm) * sf[0];
        r0.y = (acc[j][1] + fbm) * sf[1];
        r0.z = (acc[j][2] + fbm) * sf[2];
        r0.w = (acc[j][3] + fbm) * sf[3];
        r1.x = (acc[j][4] + fbm) * sf[4];
        r1.y = (acc[j][5] + fbm) * sf[5];
        r1.z = (acc[j][6] + fbm) * sf[6];
        r1.w = (acc[j][7] + fbm) * sf[7];
        float* up = &g_u[(m0 + j) * PTOT + g0 + col0];
        *(float4*)(up)     = r0;
        *(float4*)(up + 4) = r1;
    }
}

// ---------------------------------------------------------------------------
// K3: out[96][P] = proj_w[96][96] @ U + pb + anchor
// ---------------------------------------------------------------------------
__global__ void __launch_bounds__(256)
k3_proj(const float* __restrict__ Pw, const float* __restrict__ pbias,
        const float* __restrict__ anchor, float* __restrict__ out)
{
    __shared__ float Ps[C_ * 97];    // transposed [c][d], pitch 97
    __shared__ float Bs[16 * 132];

    int g0 = blockIdx.x * PB;
    int n  = g0 / HW_;
    int p0 = g0 % HW_;
    int tx = threadIdx.x;
    int m0   = (tx >> 4) * 6;
    int col0 = (tx & 15) * 8;

    for (int i = tx; i < C_ * C_; i += 256) {
        int d = i / C_, c = i % C_;
        Ps[c * 97 + d] = Pw[i];
    }

    float acc[6][8];
#pragma unroll
    for (int j = 0; j < 6; j++)
#pragma unroll
        for (int jj = 0; jj < 8; jj++) acc[j][jj] = 0.0f;

    for (int cb = 0; cb < C_; cb += 16) {
        for (int i = tx; i < 16 * PB; i += 256) {
            int kk = i >> 7, col = i & 127;
            Bs[kk * 132 + col] = g_u[(cb + kk) * PTOT + g0 + col];
        }
        __syncthreads();
#pragma unroll
        for (int kk = 0; kk < 16; kk++) {
            float a[6];
#pragma unroll
            for (int j = 0; j < 6; j++) a[j] = Ps[(cb + kk) * 97 + m0 + j];
            float4 b0 = *(const float4*)&Bs[kk * 132 + col0];
            float4 b1 = *(const float4*)&Bs[kk * 132 + col0 + 4];
            float bb[8] = {b0.x, b0.y, b0.z, b0.w, b1.x, b1.y, b1.z, b1.w};
#pragma unroll
            for (int j = 0; j < 6; j++)
#pragma unroll
                for (int jj = 0; jj < 8; jj++)
                    acc[j][jj] = fmaf(a[j], bb[jj], acc[j][jj]);
        }
        __syncthreads();
    }

#pragma unroll
    for (int j = 0; j < 6; j++) {
        int d = m0 + j;
        float pbd = pbias[d];
        const float* an = anchor + (n * C_ + d) * HW_ + p0 + col0;
        float4 a0 = *(const float4*)(an);
        float4 a1 = *(const float4*)(an + 4);
        float4 r0, r1;
        r0.x = acc[j][0] + pbd + a0.x;
        r0.y = acc[j][1] + pbd + a0.y;
        r0.z = acc[j][2] + pbd + a0.z;
        r0.w = acc[j][3] + pbd + a0.w;
        r1.x = acc[j][4] + pbd + a1.x;
        r1.y = acc[j][5] + pbd + a1.y;
        r1.z = acc[j][6] + pbd + a1.z;
        r1.w = acc[j][7] + pbd + a1.w;
        float* op = out + (n * C_ + d) * HW_ + p0 + col0;
        *(float4*)(op)     = r0;
        *(float4*)(op + 4) = r1;
    }
}

// ---------------------------------------------------------------------------
extern "C" void kernel_launch(void* const* d_in, const int* in_sizes, int n_in,
                              void* d_out, int out_size)
{
    const float* curr   = (const float*)d_in[0];
    const float* idxf   = (const float*)d_in[1];
    const float* anchor = (const float*)d_in[2];
    const float* s1     = (const float*)d_in[3];
    const float* s2     = (const float*)d_in[4];
    const float* s3     = (const float*)d_in[5];
    const float* loc    = (const float*)d_in[6];
    const float* pw     = (const float*)d_in[7];
    const float* pbv    = (const float*)d_in[8];
    const float* fw     = (const float*)d_in[9];
    const float* fbv    = (const float*)d_in[10];
    float* out = (float*)d_out;

    k1_corr<<<PTOT / 128, 128>>>(curr, idxf, s1, s2, s3, loc);
    k2_fusion<<<PTOT / PB, 256>>>(fw, fbv);
    k3_proj<<<PTOT / PB, 256>>>(pw, pbv, anchor, out);
}

// round 2
// speedup vs baseline: 1.2951x; 1.2951x over previous
#include <cuda_runtime.h>

// Problem constants
#define N_    2
#define T_    7
#define C_    96
#define HW_   9216
#define W_    96
#define PTOT  18432      // N_*HW_
#define NHEAD 4
#define HD_   24
#define K3C   288        // 3*C_

// Scratch (static device arrays; no runtime allocation)
__device__ float g_kT[N_ * T_ * HW_ * C_];   // transposed index feats: [(n,t)][pix][c]
__device__ float g_cat[K3C * PTOT];          // [k][g]  k = set*96 + channel
__device__ float g_soft[NHEAD * PTOT];       // [head][g]
__device__ float g_u[C_ * PTOT];             // [c][g]

// ---------------------------------------------------------------------------
// K0: transpose idxf (n,t,c,hw) -> g_kT ((n,t),hw,c) so per-pixel channel
//     reads become contiguous float4s.
// ---------------------------------------------------------------------------
__global__ void __launch_bounds__(256)
k0_transpose(const float* __restrict__ idxf)
{
    __shared__ float tile[32][33];
    int nt = blockIdx.z;            // 0..13
    int c0 = blockIdx.y * 32;       // 0,32,64
    int p0 = blockIdx.x * 32;       // 0..9184
    int tx = threadIdx.x, ty = threadIdx.y;   // (32,8)

    const float* src = idxf + (nt * C_) * HW_;
#pragma unroll
    for (int i = 0; i < 32; i += 8)
        tile[ty + i][tx] = src[(c0 + ty + i) * HW_ + p0 + tx];
    __syncthreads();
    float* dst = g_kT + (nt * HW_ + p0) * C_;
#pragma unroll
    for (int i = 0; i < 32; i += 8)
        dst[(ty + i) * C_ + c0 + tx] = tile[tx][ty + i];
}

// ---------------------------------------------------------------------------
// K1: 8 lanes per pixel. Lanes 0..6 own frame t, compute per-head partial
//     scores; butterfly-shfl argmax (first-max); winning-frame gather spread
//     over the 8 lanes.
// ---------------------------------------------------------------------------
__device__ __forceinline__ void red8(float& bs, int& bi)
{
#pragma unroll
    for (int d = 4; d >= 1; d >>= 1) {
        float os = __shfl_xor_sync(0xffffffffu, bs, d, 8);
        int   oi = __shfl_xor_sync(0xffffffffu, bi, d, 8);
        if (os > bs || (os == bs && oi < bi)) { bs = os; bi = oi; }
    }
}

__global__ void __launch_bounds__(256)
k1_corr(const float* __restrict__ curr,
        const float* __restrict__ sp1,
        const float* __restrict__ sp2,
        const float* __restrict__ sp3,
        const float* __restrict__ loc)
{
    __shared__ float sQ[C_ * 32];    // [c][pix_in_block]

    int tx = threadIdx.x;
    int lane8 = tx & 7;
    int pb = tx >> 3;                  // pixel index within block (0..31)
    int g0 = blockIdx.x * 32;
    int g  = g0 + pb;
    int n = g / HW_;
    int p = g - n * HW_;
    int t = lane8;

    // stage q for this block's 32 pixels into smem (coalesced)
    {
        int p0 = g0 - n * HW_;         // 32 consecutive pixels, same n
        const float* qsrc = curr + n * C_ * HW_ + p0;
        for (int idx = tx; idx < C_ * 32; idx += 256) {
            int c = idx >> 5, pi = idx & 31;
            sQ[idx] = qsrc[c * HW_ + pi];
        }
    }

    // nearest-neighbor sample location for this lane's frame
    bool val = false;
    int lin = 0;
    if (t < T_) {
        float lx = loc[(n * 2 * T_ + 2 * t) * HW_ + p];
        float ly = loc[(n * 2 * T_ + 2 * t + 1) * HW_ + p];
        float gx = __fadd_rn(__fdiv_rn(__fmul_rn(2.0f, lx), 95.0f), -1.0f);
        float gy = __fadd_rn(__fdiv_rn(__fmul_rn(2.0f, ly), 95.0f), -1.0f);
        float ixf = rintf(__fmul_rn(__fmul_rn(__fadd_rn(gx, 1.0f), 0.5f), 95.0f));
        float iyf = rintf(__fmul_rn(__fmul_rn(__fadd_rn(gy, 1.0f), 0.5f), 95.0f));
        val = (ixf >= 0.0f) && (ixf <= 95.0f) && (iyf >= 0.0f) && (iyf <= 95.0f);
        int ix = (int)fminf(fmaxf(ixf, 0.0f), 95.0f);
        int iy = (int)fminf(fmaxf(iyf, 0.0f), 95.0f);
        lin = iy * W_ + ix;
    }
    __syncthreads();

    float sA = 0.f, sB = 0.f, sC = 0.f, sD = 0.f;   // per-head dot partials
    float ksq = 0.f, qsq = 0.f;
    bool doK = (t < T_) && val;
    const float4* kp = (const float4*)(g_kT + ((n * T_ + t) * HW_ + lin) * C_);
    const float* qs = sQ + pb;

#pragma unroll
    for (int c4 = 0; c4 < 24; c4++) {
        float4 k4 = doK ? kp[c4] : make_float4(0.f, 0.f, 0.f, 0.f);
        int c = c4 * 4;
        float q0 = qs[(c + 0) * 32];
        float q1 = qs[(c + 1) * 32];
        float q2 = qs[(c + 2) * 32];
        float q3 = qs[(c + 3) * 32];
        qsq = fmaf(q0, q0, fmaf(q1, q1, fmaf(q2, q2, fmaf(q3, q3, qsq))));
        ksq = fmaf(k4.x, k4.x, fmaf(k4.y, k4.y, fmaf(k4.z, k4.z, fmaf(k4.w, k4.w, ksq))));
        float d = fmaf(q0, k4.x, fmaf(q1, k4.y, fmaf(q2, k4.z, q3 * k4.w)));
        if      (c4 <  6) sA += d;
        else if (c4 < 12) sB += d;
        else if (c4 < 18) sC += d;
        else              sD += d;
    }

    // scores (rq is a positive common factor: apply only to the soft value)
    float rk = 1.0f / fmaxf(sqrtf(ksq), 1e-12f);
    float NEGINF = __int_as_float(0xff800000);
    float b0 = (t < T_) ? sA * rk : NEGINF;
    float b1 = (t < T_) ? sB * rk : NEGINF;
    float b2 = (t < T_) ? sC * rk : NEGINF;
    float b3 = (t < T_) ? sD * rk : NEGINF;
    int i0 = t, i1 = t, i2 = t, i3 = t;
    red8(b0, i0);
    red8(b1, i1);
    red8(b2, i2);
    red8(b3, i3);

    float rq = 1.0f / fmaxf(sqrtf(qsq), 1e-12f);
    if (lane8 == 0) g_soft[0 * PTOT + g] = b0 * rq;
    if (lane8 == 1) g_soft[1 * PTOT + g] = b1 * rq;
    if (lane8 == 2) g_soft[2 * PTOT + g] = b2 * rq;
    if (lane8 == 3) g_soft[3 * PTOT + g] = b3 * rq;

    // fetch winning lane's (lin, valid) per head
    int vflag = val ? 1 : 0;
    int lw0 = __shfl_sync(0xffffffffu, lin,   i0, 8);
    int vw0 = __shfl_sync(0xffffffffu, vflag, i0, 8);
    int lw1 = __shfl_sync(0xffffffffu, lin,   i1, 8);
    int vw1 = __shfl_sync(0xffffffffu, vflag, i1, 8);
    int lw2 = __shfl_sync(0xffffffffu, lin,   i2, 8);
    int vw2 = __shfl_sync(0xffffffffu, vflag, i2, 8);
    int lw3 = __shfl_sync(0xffffffffu, lin,   i3, 8);
    int vw3 = __shfl_sync(0xffffffffu, vflag, i3, 8);

    // winning-frame gather: 72 values per head, spread over the 8 lanes
#pragma unroll
    for (int h = 0; h < NHEAD; h++) {
        int bi, lw, vw;
        if      (h == 0) { bi = i0; lw = lw0; vw = vw0; }
        else if (h == 1) { bi = i1; lw = lw1; vw = vw1; }
        else if (h == 2) { bi = i2; lw = lw2; vw = vw2; }
        else             { bi = i3; lw = lw3; vw = vw3; }
        int bofs = ((n * T_ + bi) * C_ + h * HD_) * HW_ + lw;
#pragma unroll
        for (int j = 0; j < 9; j++) {
            int i = lane8 + j * 8;          // 0..71
            int set = i / HD_;
            int cc  = i - set * HD_;
            const float* sp = (set == 0) ? sp1 : ((set == 1) ? sp2 : sp3);
            float v = vw ? __ldg(sp + bofs + cc * HW_) : 0.0f;
            g_cat[(set * C_ + h * HD_ + cc) * PTOT + g] = v;
        }
    }
}

// ---------------------------------------------------------------------------
// K2: U[96][P] = fusion_w[96][288] @ cat[288][P] + fb, scaled by per-head soft
// ---------------------------------------------------------------------------
#define PB 128
#define KB 32

__global__ void __launch_bounds__(256)
k2_fusion(const float* __restrict__ Fw, const float* __restrict__ fb)
{
    __shared__ float As[KB * 100];   // [kk][m], pitch 100
    __shared__ float Bs[KB * 132];   // [kk][col], pitch 132

    int g0 = blockIdx.x * PB;
    int tx = threadIdx.x;
    int m0   = (tx >> 4) * 6;
    int col0 = (tx & 15) * 8;

    float acc[6][8];
#pragma unroll
    for (int j = 0; j < 6; j++)
#pragma unroll
        for (int jj = 0; jj < 8; jj++) acc[j][jj] = 0.0f;

    for (int kb = 0; kb < K3C; kb += KB) {
        for (int i = tx; i < C_ * KB; i += 256) {
            int m = i >> 5, kk = i & 31;
            As[kk * 100 + m] = Fw[m * K3C + kb + kk];
        }
        for (int i = tx; i < KB * PB; i += 256) {
            int kk = i >> 7, col = i & 127;
            Bs[kk * 132 + col] = g_cat[(kb + kk) * PTOT + g0 + col];
        }
        __syncthreads();
#pragma unroll
        for (int kk = 0; kk < KB; kk++) {
            float a[6];
#pragma unroll
            for (int j = 0; j < 6; j++) a[j] = As[kk * 100 + m0 + j];
            float4 b0 = *(const float4*)&Bs[kk * 132 + col0];
            float4 b1 = *(const float4*)&Bs[kk * 132 + col0 + 4];
            float bb[8] = {b0.x, b0.y, b0.z, b0.w, b1.x, b1.y, b1.z, b1.w};
#pragma unroll
            for (int j = 0; j < 6; j++)
#pragma unroll
                for (int jj = 0; jj < 8; jj++)
                    acc[j][jj] = fmaf(a[j], bb[jj], acc[j][jj]);
        }
        __syncthreads();
    }

    int head = m0 / HD_;
    float sf[8];
#pragma unroll
    for (int jj = 0; jj < 8; jj++) sf[jj] = g_soft[head * PTOT + g0 + col0 + jj];

#pragma unroll
    for (int j = 0; j < 6; j++) {
        float fbm = fb[m0 + j];
        float4 r0, r1;
        r0.x = (acc[j][0] + fbm) * sf[0];
        r0.y = (acc[j][1] + fbm) * sf[1];
        r0.z = (acc[j][2] + fbm) * sf[2];
        r0.w = (acc[j][3] + fbm) * sf[3];
        r1.x = (acc[j][4] + fbm) * sf[4];
        r1.y = (acc[j][5] + fbm) * sf[5];
        r1.z = (acc[j][6] + fbm) * sf[6];
        r1.w = (acc[j][7] + fbm) * sf[7];
        float* up = &g_u[(m0 + j) * PTOT + g0 + col0];
        *(float4*)(up)     = r0;
        *(float4*)(up + 4) = r1;
    }
}

// ---------------------------------------------------------------------------
// K3: out[96][P] = proj_w[96][96] @ U + pb + anchor
// ---------------------------------------------------------------------------
__global__ void __launch_bounds__(256)
k3_proj(const float* __restrict__ Pw, const float* __restrict__ pbias,
        const float* __restrict__ anchor, float* __restrict__ out)
{
    __shared__ float Ps[C_ * 97];
    __shared__ float Bs[16 * 132];

    int g0 = blockIdx.x * PB;
    int n  = g0 / HW_;
    int p0 = g0 % HW_;
    int tx = threadIdx.x;
    int m0   = (tx >> 4) * 6;
    int col0 = (tx & 15) * 8;

    for (int i = tx; i < C_ * C_; i += 256) {
        int d = i / C_, c = i % C_;
        Ps[c * 97 + d] = Pw[i];
    }

    float acc[6][8];
#pragma unroll
    for (int j = 0; j < 6; j++)
#pragma unroll
        for (int jj = 0; jj < 8; jj++) acc[j][jj] = 0.0f;

    for (int cb = 0; cb < C_; cb += 16) {
        for (int i = tx; i < 16 * PB; i += 256) {
            int kk = i >> 7, col = i & 127;
            Bs[kk * 132 + col] = g_u[(cb + kk) * PTOT + g0 + col];
        }
        __syncthreads();
#pragma unroll
        for (int kk = 0; kk < 16; kk++) {
            float a[6];
#pragma unroll
            for (int j = 0; j < 6; j++) a[j] = Ps[(cb + kk) * 97 + m0 + j];
            float4 b0 = *(const float4*)&Bs[kk * 132 + col0];
            float4 b1 = *(const float4*)&Bs[kk * 132 + col0 + 4];
            float bb[8] = {b0.x, b0.y, b0.z, b0.w, b1.x, b1.y, b1.z, b1.w};
#pragma unroll
            for (int j = 0; j < 6; j++)
#pragma unroll
                for (int jj = 0; jj < 8; jj++)
                    acc[j][jj] = fmaf(a[j], bb[jj], acc[j][jj]);
        }
        __syncthreads();
    }

#pragma unroll
    for (int j = 0; j < 6; j++) {
        int d = m0 + j;
        float pbd = pbias[d];
        const float* an = anchor + (n * C_ + d) * HW_ + p0 + col0;
        float4 a0 = *(const float4*)(an);
        float4 a1 = *(const float4*)(an + 4);
        float4 r0, r1;
        r0.x = acc[j][0] + pbd + a0.x;
        r0.y = acc[j][1] + pbd + a0.y;
        r0.z = acc[j][2] + pbd + a0.z;
        r0.w = acc[j][3] + pbd + a0.w;
        r1.x = acc[j][4] + pbd + a1.x;
        r1.y = acc[j][5] + pbd + a1.y;
        r1.z = acc[j][6] + pbd + a1.z;
        r1.w = acc[j][7] + pbd + a1.w;
        float* op = out + (n * C_ + d) * HW_ + p0 + col0;
        *(float4*)(op)     = r0;
        *(float4*)(op + 4) = r1;
    }
}

// ---------------------------------------------------------------------------
extern "C" void kernel_launch(void* const* d_in, const int* in_sizes, int n_in,
                              void* d_out, int out_size)
{
    const float* curr   = (const float*)d_in[0];
    const float* idxf   = (const float*)d_in[1];
    const float* anchor = (const float*)d_in[2];
    const float* s1     = (const float*)d_in[3];
    const float* s2     = (const float*)d_in[4];
    const float* s3     = (const float*)d_in[5];
    const float* loc    = (const float*)d_in[6];
    const float* pw     = (const float*)d_in[7];
    const float* pbv    = (const float*)d_in[8];
    const float* fw     = (const float*)d_in[9];
    const float* fbv    = (const float*)d_in[10];
    float* out = (float*)d_out;

    k0_transpose<<<dim3(HW_ / 32, C_ / 32, N_ * T_), dim3(32, 8)>>>(idxf);
    k1_corr<<<PTOT / 32, 256>>>(curr, s1, s2, s3, loc);
    k2_fusion<<<PTOT / PB, 256>>>(fw, fbv);
    k3_proj<<<PTOT / PB, 256>>>(pw, pbv, anchor, out);
}

// round 3
// speedup vs baseline: 1.5912x; 1.2287x over previous
#include <cuda_runtime.h>

// Problem constants
#define N_    2
#define T_    7
#define C_    96
#define HW_   9216
#define W_    96
#define PTOT  18432      // N_*HW_
#define NHEAD 4
#define HD_   24
#define K3C   288        // 3*C_

// Scratch (static device arrays; no runtime allocation)
__device__ float g_kT[N_ * T_ * HW_ * C_];   // transposed index feats: [(n,t)][pix][c]
__device__ float g_cat[PTOT * K3C];          // [g][k]  k = set*96 + channel
__device__ float g_soft[NHEAD * PTOT];       // [head][g]

// ---------------------------------------------------------------------------
// K0: transpose idxf (n,t,c,hw) -> g_kT ((n,t),hw,c)
// ---------------------------------------------------------------------------
__global__ void __launch_bounds__(256)
k0_transpose(const float* __restrict__ idxf)
{
    __shared__ float tile[32][33];
    int nt = blockIdx.z;
    int c0 = blockIdx.y * 32;
    int p0 = blockIdx.x * 32;
    int tx = threadIdx.x, ty = threadIdx.y;   // (32,8)

    const float* src = idxf + (nt * C_) * HW_;
#pragma unroll
    for (int i = 0; i < 32; i += 8)
        tile[ty + i][tx] = src[(c0 + ty + i) * HW_ + p0 + tx];
    __syncthreads();
    float* dst = g_kT + (nt * HW_ + p0) * C_;
#pragma unroll
    for (int i = 0; i < 32; i += 8)
        dst[(ty + i) * C_ + c0 + tx] = tile[tx][ty + i];
}

// ---------------------------------------------------------------------------
// K1: 8 lanes per pixel; lanes 0..6 own frame t; shfl argmax (first-max);
//     winning-frame gather spread over lanes; cat stored pixel-major.
// ---------------------------------------------------------------------------
__device__ __forceinline__ void red8(float& bs, int& bi)
{
#pragma unroll
    for (int d = 4; d >= 1; d >>= 1) {
        float os = __shfl_xor_sync(0xffffffffu, bs, d, 8);
        int   oi = __shfl_xor_sync(0xffffffffu, bi, d, 8);
        if (os > bs || (os == bs && oi < bi)) { bs = os; bi = oi; }
    }
}

__global__ void __launch_bounds__(256)
k1_corr(const float* __restrict__ curr,
        const float* __restrict__ sp1,
        const float* __restrict__ sp2,
        const float* __restrict__ sp3,
        const float* __restrict__ loc)
{
    __shared__ float sQ[C_ * 32];    // [c][pix_in_block]

    int tx = threadIdx.x;
    int lane8 = tx & 7;
    int pb = tx >> 3;
    int g0 = blockIdx.x * 32;
    int g  = g0 + pb;
    int n = g / HW_;
    int p = g - n * HW_;
    int t = lane8;

    {
        int p0 = g0 - n * HW_;
        const float* qsrc = curr + n * C_ * HW_ + p0;
        for (int idx = tx; idx < C_ * 32; idx += 256) {
            int c = idx >> 5, pi = idx & 31;
            sQ[idx] = qsrc[c * HW_ + pi];
        }
    }

    bool val = false;
    int lin = 0;
    if (t < T_) {
        float lx = loc[(n * 2 * T_ + 2 * t) * HW_ + p];
        float ly = loc[(n * 2 * T_ + 2 * t + 1) * HW_ + p];
        float gx = __fadd_rn(__fdiv_rn(__fmul_rn(2.0f, lx), 95.0f), -1.0f);
        float gy = __fadd_rn(__fdiv_rn(__fmul_rn(2.0f, ly), 95.0f), -1.0f);
        float ixf = rintf(__fmul_rn(__fmul_rn(__fadd_rn(gx, 1.0f), 0.5f), 95.0f));
        float iyf = rintf(__fmul_rn(__fmul_rn(__fadd_rn(gy, 1.0f), 0.5f), 95.0f));
        val = (ixf >= 0.0f) && (ixf <= 95.0f) && (iyf >= 0.0f) && (iyf <= 95.0f);
        int ix = (int)fminf(fmaxf(ixf, 0.0f), 95.0f);
        int iy = (int)fminf(fmaxf(iyf, 0.0f), 95.0f);
        lin = iy * W_ + ix;
    }
    __syncthreads();

    float sA = 0.f, sB = 0.f, sC = 0.f, sD = 0.f;
    float ksq = 0.f, qsq = 0.f;
    bool doK = (t < T_) && val;
    const float4* kp = (const float4*)(g_kT + ((n * T_ + t) * HW_ + lin) * C_);
    const float* qs = sQ + pb;

#pragma unroll
    for (int c4 = 0; c4 < 24; c4++) {
        float4 k4 = doK ? kp[c4] : make_float4(0.f, 0.f, 0.f, 0.f);
        int c = c4 * 4;
        float q0 = qs[(c + 0) * 32];
        float q1 = qs[(c + 1) * 32];
        float q2 = qs[(c + 2) * 32];
        float q3 = qs[(c + 3) * 32];
        qsq = fmaf(q0, q0, fmaf(q1, q1, fmaf(q2, q2, fmaf(q3, q3, qsq))));
        ksq = fmaf(k4.x, k4.x, fmaf(k4.y, k4.y, fmaf(k4.z, k4.z, fmaf(k4.w, k4.w, ksq))));
        float d = fmaf(q0, k4.x, fmaf(q1, k4.y, fmaf(q2, k4.z, q3 * k4.w)));
        if      (c4 <  6) sA += d;
        else if (c4 < 12) sB += d;
        else if (c4 < 18) sC += d;
        else              sD += d;
    }

    float rk = 1.0f / fmaxf(sqrtf(ksq), 1e-12f);
    float NEGINF = __int_as_float(0xff800000);
    float b0 = (t < T_) ? sA * rk : NEGINF;
    float b1 = (t < T_) ? sB * rk : NEGINF;
    float b2 = (t < T_) ? sC * rk : NEGINF;
    float b3 = (t < T_) ? sD * rk : NEGINF;
    int i0 = t, i1 = t, i2 = t, i3 = t;
    red8(b0, i0);
    red8(b1, i1);
    red8(b2, i2);
    red8(b3, i3);

    float rq = 1.0f / fmaxf(sqrtf(qsq), 1e-12f);
    if (lane8 == 0) g_soft[0 * PTOT + g] = b0 * rq;
    if (lane8 == 1) g_soft[1 * PTOT + g] = b1 * rq;
    if (lane8 == 2) g_soft[2 * PTOT + g] = b2 * rq;
    if (lane8 == 3) g_soft[3 * PTOT + g] = b3 * rq;

    int vflag = val ? 1 : 0;
    int lw0 = __shfl_sync(0xffffffffu, lin,   i0, 8);
    int vw0 = __shfl_sync(0xffffffffu, vflag, i0, 8);
    int lw1 = __shfl_sync(0xffffffffu, lin,   i1, 8);
    int vw1 = __shfl_sync(0xffffffffu, vflag, i1, 8);
    int lw2 = __shfl_sync(0xffffffffu, lin,   i2, 8);
    int vw2 = __shfl_sync(0xffffffffu, vflag, i2, 8);
    int lw3 = __shfl_sync(0xffffffffu, lin,   i3, 8);
    int vw3 = __shfl_sync(0xffffffffu, vflag, i3, 8);

    float* catg = g_cat + (size_t)g * K3C;
#pragma unroll
    for (int h = 0; h < NHEAD; h++) {
        int bi, lw, vw;
        if      (h == 0) { bi = i0; lw = lw0; vw = vw0; }
        else if (h == 1) { bi = i1; lw = lw1; vw = vw1; }
        else if (h == 2) { bi = i2; lw = lw2; vw = vw2; }
        else             { bi = i3; lw = lw3; vw = vw3; }
        int bofs = ((n * T_ + bi) * C_ + h * HD_) * HW_ + lw;
#pragma unroll
        for (int j = 0; j < 9; j++) {
            int i = lane8 + j * 8;          // 0..71
            int set = i / HD_;
            int cc  = i - set * HD_;
            const float* sp = (set == 0) ? sp1 : ((set == 1) ? sp2 : sp3);
            float v = vw ? __ldg(sp + bofs + cc * HW_) : 0.0f;
            catg[set * C_ + h * HD_ + cc] = v;     // pixel-major: ~contiguous per 8 lanes
        }
    }
}

// ---------------------------------------------------------------------------
// K23 fused: U = (Fw @ cat + fb) * soft  (held in smem);
//            out = Pw @ U + pb + anchor
// ---------------------------------------------------------------------------
#define PB 64
#define KB 32
#define BP 68    // Bs/Us column pitch (17 float4s)

__global__ void __launch_bounds__(256, 3)
k23_gemm(const float* __restrict__ Fw, const float* __restrict__ fb,
         const float* __restrict__ Pw, const float* __restrict__ pbias,
         const float* __restrict__ anchor, float* __restrict__ out)
{
    __shared__ float As[KB * 100];   // weight chunk, transposed [kk][m]
    __shared__ float Bs[KB * BP];    // cat chunk [kk][col]
    __shared__ float Us[C_ * BP];    // intermediate [m][col]

    int g0 = blockIdx.x * PB;
    int n  = g0 / HW_;
    int p0 = g0 - n * HW_;
    int tx = threadIdx.x;
    int m0   = (tx >> 4) * 6;        // 16 groups * 6 = 96 rows
    int col0 = (tx & 15) * 4;        // 16 groups * 4 = 64 cols

    float acc[6][4];
#pragma unroll
    for (int j = 0; j < 6; j++)
#pragma unroll
        for (int jj = 0; jj < 4; jj++) acc[j][jj] = 0.0f;

    // ---- phase 1: U = Fw @ cat ----
    const float4* cat4 = (const float4*)g_cat;
    for (int kb = 0; kb < K3C; kb += KB) {
        for (int i = tx; i < C_ * KB; i += 256) {
            int m = i >> 5, kk = i & 31;
            As[kk * 100 + m] = Fw[m * K3C + kb + kk];
        }
        // Bs[kk][col] = cat[(g0+col)][kb+kk] ; rows of cat are contiguous
        for (int i = tx; i < PB * 8; i += 256) {
            int col = i >> 3, k4 = i & 7;
            float4 v = cat4[(size_t)(g0 + col) * (K3C / 4) + (kb >> 2) + k4];
            int kk = k4 * 4;
            Bs[(kk + 0) * BP + col] = v.x;
            Bs[(kk + 1) * BP + col] = v.y;
            Bs[(kk + 2) * BP + col] = v.z;
            Bs[(kk + 3) * BP + col] = v.w;
        }
        __syncthreads();
#pragma unroll
        for (int kk = 0; kk < KB; kk++) {
            float a[6];
#pragma unroll
            for (int j = 0; j < 6; j++) a[j] = As[kk * 100 + m0 + j];
            float4 b = *(const float4*)&Bs[kk * BP + col0];
#pragma unroll
            for (int j = 0; j < 6; j++) {
                acc[j][0] = fmaf(a[j], b.x, acc[j][0]);
                acc[j][1] = fmaf(a[j], b.y, acc[j][1]);
                acc[j][2] = fmaf(a[j], b.z, acc[j][2]);
                acc[j][3] = fmaf(a[j], b.w, acc[j][3]);
            }
        }
        __syncthreads();
    }

    // epilogue 1: +fb, *soft -> Us
    {
        int head = m0 / HD_;
        float4 sf = *(const float4*)&g_soft[head * PTOT + g0 + col0];
        // note: g_soft rows are PTOT-long; col0*4B alignment ok (col0 mult of 4)
#pragma unroll
        for (int j = 0; j < 6; j++) {
            float fbm = fb[m0 + j];
            float4 r;
            r.x = (acc[j][0] + fbm) * sf.x;
            r.y = (acc[j][1] + fbm) * sf.y;
            r.z = (acc[j][2] + fbm) * sf.z;
            r.w = (acc[j][3] + fbm) * sf.w;
            *(float4*)&Us[(m0 + j) * BP + col0] = r;
        }
    }
    __syncthreads();

    // ---- phase 2: out = Pw @ U ----
    float acc2[6][4];
#pragma unroll
    for (int j = 0; j < 6; j++)
#pragma unroll
        for (int jj = 0; jj < 4; jj++) acc2[j][jj] = 0.0f;

    for (int cb = 0; cb < C_; cb += KB) {
        for (int i = tx; i < C_ * KB; i += 256) {
            int d = i >> 5, kk = i & 31;
            As[kk * 100 + d] = Pw[d * C_ + cb + kk];
        }
        __syncthreads();
#pragma unroll
        for (int kk = 0; kk < KB; kk++) {
            float a[6];
#pragma unroll
            for (int j = 0; j < 6; j++) a[j] = As[kk * 100 + m0 + j];
            float4 b = *(const float4*)&Us[(cb + kk) * BP + col0];
#pragma unroll
            for (int j = 0; j < 6; j++) {
                acc2[j][0] = fmaf(a[j], b.x, acc2[j][0]);
                acc2[j][1] = fmaf(a[j], b.y, acc2[j][1]);
                acc2[j][2] = fmaf(a[j], b.z, acc2[j][2]);
                acc2[j][3] = fmaf(a[j], b.w, acc2[j][3]);
            }
        }
        __syncthreads();
    }

    // epilogue 2: + pbias + anchor -> out
#pragma unroll
    for (int j = 0; j < 6; j++) {
        int d = m0 + j;
        float pbd = pbias[d];
        float4 a0 = *(const float4*)(anchor + (size_t)(n * C_ + d) * HW_ + p0 + col0);
        float4 r;
        r.x = acc2[j][0] + pbd + a0.x;
        r.y = acc2[j][1] + pbd + a0.y;
        r.z = acc2[j][2] + pbd + a0.z;
        r.w = acc2[j][3] + pbd + a0.w;
        *(float4*)(out + (size_t)(n * C_ + d) * HW_ + p0 + col0) = r;
    }
}

// ---------------------------------------------------------------------------
extern "C" void kernel_launch(void* const* d_in, const int* in_sizes, int n_in,
                              void* d_out, int out_size)
{
    const float* curr   = (const float*)d_in[0];
    const float* idxf   = (const float*)d_in[1];
    const float* anchor = (const float*)d_in[2];
    const float* s1     = (const float*)d_in[3];
    const float* s2     = (const float*)d_in[4];
    const float* s3     = (const float*)d_in[5];
    const float* loc    = (const float*)d_in[6];
    const float* pw     = (const float*)d_in[7];
    const float* pbv    = (const float*)d_in[8];
    const float* fw     = (const float*)d_in[9];
    const float* fbv    = (const float*)d_in[10];
    float* out = (float*)d_out;

    k0_transpose<<<dim3(HW_ / 32, C_ / 32, N_ * T_), dim3(32, 8)>>>(idxf);
    k1_corr<<<PTOT / 32, 256>>>(curr, s1, s2, s3, loc);
    k23_gemm<<<PTOT / PB, 256>>>(fw, fbv, pw, pbv, anchor, out);
}

// round 4
// speedup vs baseline: 1.7251x; 1.0842x over previous
#include <cuda_runtime.h>

// Problem constants
#define N_    2
#define T_    7
#define C_    96
#define HW_   9216
#define W_    96
#define PTOT  18432      // N_*HW_
#define NHEAD 4
#define HD_   24
#define K3C   288        // 3*C_

// Scratch (static device arrays; no runtime allocation)
__device__ float g_kT[N_ * T_ * HW_ * C_];   // transposed index feats: [(n,t)][pix][c]
__device__ float g_cat[PTOT * K3C];          // [g][k]  k = set*96 + channel
__device__ float g_soft[NHEAD * PTOT];       // [head][g]

// ---------------------------------------------------------------------------
// K0: transpose idxf (n,t,c,hw) -> g_kT ((n,t),hw,c)
// ---------------------------------------------------------------------------
__global__ void __launch_bounds__(256)
k0_transpose(const float* __restrict__ idxf)
{
    __shared__ float tile[32][33];
    int nt = blockIdx.z;
    int c0 = blockIdx.y * 32;
    int p0 = blockIdx.x * 32;
    int tx = threadIdx.x, ty = threadIdx.y;   // (32,8)

    const float* src = idxf + (nt * C_) * HW_;
#pragma unroll
    for (int i = 0; i < 32; i += 8)
        tile[ty + i][tx] = src[(c0 + ty + i) * HW_ + p0 + tx];
    __syncthreads();
    float* dst = g_kT + (nt * HW_ + p0) * C_;
#pragma unroll
    for (int i = 0; i < 32; i += 8)
        dst[(ty + i) * C_ + c0 + tx] = tile[tx][ty + i];
}

// ---------------------------------------------------------------------------
// K1: 8 lanes per pixel; lanes 0..6 own frame t; shfl argmax (first-max);
//     division-free winner gather spread over lanes; cat stored pixel-major.
// ---------------------------------------------------------------------------
__device__ __forceinline__ void red8(float& bs, int& bi)
{
#pragma unroll
    for (int d = 4; d >= 1; d >>= 1) {
        float os = __shfl_xor_sync(0xffffffffu, bs, d, 8);
        int   oi = __shfl_xor_sync(0xffffffffu, bi, d, 8);
        if (os > bs || (os == bs && oi < bi)) { bs = os; bi = oi; }
    }
}

__global__ void __launch_bounds__(256)
k1_corr(const float* __restrict__ curr,
        const float* __restrict__ sp1,
        const float* __restrict__ sp2,
        const float* __restrict__ sp3,
        const float* __restrict__ loc)
{
    __shared__ __align__(16) float sQ[32 * 100];   // [pix][c], pitch 100 (16B-aligned rows)
    __shared__ float sLoc[2 * T_][32];             // [plane][pix]

    int tx = threadIdx.x;
    int lane8 = tx & 7;
    int pb = tx >> 3;
    int g0 = blockIdx.x * 32;
    int g  = g0 + pb;
    int n = g / HW_;
    int p0blk = g0 - n * HW_;     // block's 32 pixels share n (HW_ % 32 == 0)
    int t = lane8;

    // stage q (coalesced reads; transposed smem writes)
    {
        const float* qsrc = curr + n * C_ * HW_ + p0blk;
        for (int idx = tx; idx < C_ * 32; idx += 256) {
            int c = idx >> 5, pi = idx & 31;
            sQ[pi * 100 + c] = qsrc[c * HW_ + pi];
        }
    }
    // stage loc planes (coalesced)
    {
        const float* lsrc = loc + (size_t)n * 2 * T_ * HW_ + p0blk;
        for (int idx = tx; idx < 2 * T_ * 32; idx += 256) {
            int pl = idx >> 5, pi = idx & 31;
            sLoc[pl][pi] = lsrc[pl * HW_ + pi];
        }
    }
    __syncthreads();

    // nearest-neighbor sample location for this lane's frame
    bool val = false;
    int lin = 0;
    if (t < T_) {
        float lx = sLoc[2 * t][pb];
        float ly = sLoc[2 * t + 1][pb];
        float gx = __fadd_rn(__fdiv_rn(__fmul_rn(2.0f, lx), 95.0f), -1.0f);
        float gy = __fadd_rn(__fdiv_rn(__fmul_rn(2.0f, ly), 95.0f), -1.0f);
        float ixf = rintf(__fmul_rn(__fmul_rn(__fadd_rn(gx, 1.0f), 0.5f), 95.0f));
        float iyf = rintf(__fmul_rn(__fmul_rn(__fadd_rn(gy, 1.0f), 0.5f), 95.0f));
        val = (ixf >= 0.0f) && (ixf <= 95.0f) && (iyf >= 0.0f) && (iyf <= 95.0f);
        int ix = (int)fminf(fmaxf(ixf, 0.0f), 95.0f);
        int iy = (int)fminf(fmaxf(iyf, 0.0f), 95.0f);
        lin = iy * W_ + ix;
    }

    float sA = 0.f, sB = 0.f, sC = 0.f, sD = 0.f;
    float ksq = 0.f, qsq = 0.f;
    bool doK = (t < T_) && val;
    const float4* kp = (const float4*)(g_kT + ((size_t)(n * T_ + t) * HW_ + lin) * C_);
    const float* qrow = sQ + pb * 100;

#pragma unroll
    for (int c4 = 0; c4 < 24; c4++) {
        float4 k4 = doK ? kp[c4] : make_float4(0.f, 0.f, 0.f, 0.f);
        float4 q4 = *(const float4*)(qrow + c4 * 4);   // broadcast LDS.128
        qsq = fmaf(q4.x, q4.x, fmaf(q4.y, q4.y, fmaf(q4.z, q4.z, fmaf(q4.w, q4.w, qsq))));
        ksq = fmaf(k4.x, k4.x, fmaf(k4.y, k4.y, fmaf(k4.z, k4.z, fmaf(k4.w, k4.w, ksq))));
        float d = fmaf(q4.x, k4.x, fmaf(q4.y, k4.y, fmaf(q4.z, k4.z, q4.w * k4.w)));
        if      (c4 <  6) sA += d;
        else if (c4 < 12) sB += d;
        else if (c4 < 18) sC += d;
        else              sD += d;
    }

    float rk = 1.0f / fmaxf(sqrtf(ksq), 1e-12f);
    float NEGINF = __int_as_float(0xff800000);
    float b0 = (t < T_) ? sA * rk : NEGINF;
    float b1 = (t < T_) ? sB * rk : NEGINF;
    float b2 = (t < T_) ? sC * rk : NEGINF;
    float b3 = (t < T_) ? sD * rk : NEGINF;
    int i0 = t, i1 = t, i2 = t, i3 = t;
    red8(b0, i0);
    red8(b1, i1);
    red8(b2, i2);
    red8(b3, i3);

    float rq = 1.0f / fmaxf(sqrtf(qsq), 1e-12f);
    if (lane8 == 0) g_soft[0 * PTOT + g] = b0 * rq;
    if (lane8 == 1) g_soft[1 * PTOT + g] = b1 * rq;
    if (lane8 == 2) g_soft[2 * PTOT + g] = b2 * rq;
    if (lane8 == 3) g_soft[3 * PTOT + g] = b3 * rq;

    int vflag = val ? 1 : 0;
    int bw[NHEAD], lw[NHEAD], vw[NHEAD];
    bw[0] = i0; bw[1] = i1; bw[2] = i2; bw[3] = i3;
#pragma unroll
    for (int h = 0; h < NHEAD; h++) {
        lw[h] = __shfl_sync(0xffffffffu, lin,   bw[h], 8);
        vw[h] = __shfl_sync(0xffffffffu, vflag, bw[h], 8);
    }

    float* catg = g_cat + (size_t)g * K3C;
#pragma unroll
    for (int h = 0; h < NHEAD; h++) {
        int bofs = ((n * T_ + bw[h]) * C_ + h * HD_) * HW_ + lw[h];
        bool v = (vw[h] != 0);
#pragma unroll
        for (int set = 0; set < 3; set++) {
            const float* sp = (set == 0) ? sp1 : ((set == 1) ? sp2 : sp3);
#pragma unroll
            for (int j2 = 0; j2 < 3; j2++) {
                int cc = lane8 + j2 * 8;              // 0..23, division-free
                float vv = v ? __ldg(sp + bofs + cc * HW_) : 0.0f;
                catg[set * C_ + h * HD_ + cc] = vv;
            }
        }
    }
}

// ---------------------------------------------------------------------------
// K23 fused: U = (Fw @ cat + fb) * soft  (held in smem);
//            out = Pw @ U + pb + anchor.  Phase-1 gmem loads are
//            register-prefetched to overlap with FMA.
// ---------------------------------------------------------------------------
#define PB 64
#define KB 32
#define BP 68    // Bs/Us column pitch (17 float4s)

__global__ void __launch_bounds__(256, 2)
k23_gemm(const float* __restrict__ Fw, const float* __restrict__ fb,
         const float* __restrict__ Pw, const float* __restrict__ pbias,
         const float* __restrict__ anchor, float* __restrict__ out)
{
    __shared__ float As[KB * 100];   // weight chunk, transposed [kk][m]
    __shared__ float Bs[KB * BP];    // cat chunk [kk][col]
    __shared__ float Us[C_ * BP];    // intermediate [m][col]

    int g0 = blockIdx.x * PB;
    int n  = g0 / HW_;
    int p0 = g0 - n * HW_;
    int tx = threadIdx.x;
    int m0   = (tx >> 4) * 6;        // 16 groups * 6 = 96 rows
    int col0 = (tx & 15) * 4;        // 16 groups * 4 = 64 cols

    float acc[6][4];
#pragma unroll
    for (int j = 0; j < 6; j++)
#pragma unroll
        for (int jj = 0; jj < 4; jj++) acc[j][jj] = 0.0f;

    const float4* cat4 = (const float4*)g_cat;

    // register prefetch buffers
    float  aR[12];     // 3072 / 256
    float4 bR[2];      // 512 / 256

    // load kb = 0
#pragma unroll
    for (int r = 0; r < 12; r++) {
        int i = r * 256 + tx;
        aR[r] = Fw[(i >> 5) * K3C + (i & 31)];
    }
#pragma unroll
    for (int r = 0; r < 2; r++) {
        int i = r * 256 + tx;
        bR[r] = cat4[(size_t)(g0 + (i >> 3)) * (K3C / 4) + (i & 7)];
    }

    // ---- phase 1: U = Fw @ cat ----
    for (int kb = 0; kb < K3C; kb += KB) {
        // commit prefetched chunk to smem
#pragma unroll
        for (int r = 0; r < 12; r++) {
            int i = r * 256 + tx;
            As[(i & 31) * 100 + (i >> 5)] = aR[r];
        }
#pragma unroll
        for (int r = 0; r < 2; r++) {
            int i = r * 256 + tx;
            int col = i >> 3, kk = (i & 7) * 4;
            Bs[(kk + 0) * BP + col] = bR[r].x;
            Bs[(kk + 1) * BP + col] = bR[r].y;
            Bs[(kk + 2) * BP + col] = bR[r].z;
            Bs[(kk + 3) * BP + col] = bR[r].w;
        }
        __syncthreads();

        // prefetch next chunk while computing
        int kn = kb + KB;
        if (kn < K3C) {
#pragma unroll
            for (int r = 0; r < 12; r++) {
                int i = r * 256 + tx;
                aR[r] = Fw[(i >> 5) * K3C + kn + (i & 31)];
            }
#pragma unroll
            for (int r = 0; r < 2; r++) {
                int i = r * 256 + tx;
                bR[r] = cat4[(size_t)(g0 + (i >> 3)) * (K3C / 4) + (kn >> 2) + (i & 7)];
            }
        }

#pragma unroll
        for (int kk = 0; kk < KB; kk++) {
            float a[6];
#pragma unroll
            for (int j = 0; j < 6; j++) a[j] = As[kk * 100 + m0 + j];
            float4 b = *(const float4*)&Bs[kk * BP + col0];
#pragma unroll
            for (int j = 0; j < 6; j++) {
                acc[j][0] = fmaf(a[j], b.x, acc[j][0]);
                acc[j][1] = fmaf(a[j], b.y, acc[j][1]);
                acc[j][2] = fmaf(a[j], b.z, acc[j][2]);
                acc[j][3] = fmaf(a[j], b.w, acc[j][3]);
            }
        }
        __syncthreads();
    }

    // epilogue 1: +fb, *soft -> Us
    {
        int head = m0 / HD_;
        float4 sf = *(const float4*)&g_soft[head * PTOT + g0 + col0];
#pragma unroll
        for (int j = 0; j < 6; j++) {
            float fbm = fb[m0 + j];
            float4 r;
            r.x = (acc[j][0] + fbm) * sf.x;
            r.y = (acc[j][1] + fbm) * sf.y;
            r.z = (acc[j][2] + fbm) * sf.z;
            r.w = (acc[j][3] + fbm) * sf.w;
            *(float4*)&Us[(m0 + j) * BP + col0] = r;
        }
    }
    __syncthreads();

    // ---- phase 2: out = Pw @ U ----
    float acc2[6][4];
#pragma unroll
    for (int j = 0; j < 6; j++)
#pragma unroll
        for (int jj = 0; jj < 4; jj++) acc2[j][jj] = 0.0f;

    for (int cb = 0; cb < C_; cb += KB) {
        for (int i = tx; i < C_ * KB; i += 256) {
            int d = i >> 5, kk = i & 31;
            As[kk * 100 + d] = Pw[d * C_ + cb + kk];
        }
        __syncthreads();
#pragma unroll
        for (int kk = 0; kk < KB; kk++) {
            float a[6];
#pragma unroll
            for (int j = 0; j < 6; j++) a[j] = As[kk * 100 + m0 + j];
            float4 b = *(const float4*)&Us[(cb + kk) * BP + col0];
#pragma unroll
            for (int j = 0; j < 6; j++) {
                acc2[j][0] = fmaf(a[j], b.x, acc2[j][0]);
                acc2[j][1] = fmaf(a[j], b.y, acc2[j][1]);
                acc2[j][2] = fmaf(a[j], b.z, acc2[j][2]);
                acc2[j][3] = fmaf(a[j], b.w, acc2[j][3]);
            }
        }
        __syncthreads();
    }

    // epilogue 2: + pbias + anchor -> out
#pragma unroll
    for (int j = 0; j < 6; j++) {
        int d = m0 + j;
        float pbd = pbias[d];
        float4 a0 = *(const float4*)(anchor + (size_t)(n * C_ + d) * HW_ + p0 + col0);
        float4 r;
        r.x = acc2[j][0] + pbd + a0.x;
        r.y = acc2[j][1] + pbd + a0.y;
        r.z = acc2[j][2] + pbd + a0.z;
        r.w = acc2[j][3] + pbd + a0.w;
        *(float4*)(out + (size_t)(n * C_ + d) * HW_ + p0 + col0) = r;
    }
}

// ---------------------------------------------------------------------------
extern "C" void kernel_launch(void* const* d_in, const int* in_sizes, int n_in,
                              void* d_out, int out_size)
{
    const float* curr   = (const float*)d_in[0];
    const float* idxf   = (const float*)d_in[1];
    const float* anchor = (const float*)d_in[2];
    const float* s1     = (const float*)d_in[3];
    const float* s2     = (const float*)d_in[4];
    const float* s3     = (const float*)d_in[5];
    const float* loc    = (const float*)d_in[6];
    const float* pw     = (const float*)d_in[7];
    const float* pbv    = (const float*)d_in[8];
    const float* fw     = (const float*)d_in[9];
    const float* fbv    = (const float*)d_in[10];
    float* out = (float*)d_out;

    k0_transpose<<<dim3(HW_ / 32, C_ / 32, N_ * T_), dim3(32, 8)>>>(idxf);
    k1_corr<<<PTOT / 32, 256>>>(curr, s1, s2, s3, loc);
    k23_gemm<<<PTOT / PB, 256>>>(fw, fbv, pw, pbv, anchor, out);
}